// round 1
// baseline (speedup 1.0000x reference)
#include <cuda_runtime.h>

#define B_   4
#define S_   2048
#define D_   512
#define H_   8
#define HD_  64
#define ROWS_ (B_ * S_)          // 8192
#define EPS_ 1e-8f

// ---------------------------------------------------------------------------
// Scratch (allocation-free rule: __device__ globals)
// ---------------------------------------------------------------------------
__device__ float g_X    [(size_t)ROWS_ * (2 * D_)];  // concat(gene, expr)
__device__ float g_fused[(size_t)ROWS_ * D_];
__device__ float g_Q    [(size_t)ROWS_ * D_];        // [B,H,S,HD]
__device__ float g_K    [(size_t)ROWS_ * D_];        // [B,H,S,HD]
__device__ float g_V    [(size_t)ROWS_ * D_];        // [B,H,S,HD]
__device__ float g_attn [(size_t)ROWS_ * D_];        // [B,S,D]

// ---------------------------------------------------------------------------
// Concat kernel: X[r, 0:512] = gene[r], X[r, 512:1024] = expr[r]
// ---------------------------------------------------------------------------
__global__ __launch_bounds__(256) void cat_kernel(
    const float* __restrict__ g, const float* __restrict__ e,
    float* __restrict__ X)
{
    int idx = blockIdx.x * 256 + threadIdx.x;   // float4 index
    int r  = idx >> 8;                          // 256 float4 per row
    int c4 = idx & 255;
    const float* src = (c4 < 128) ? (g + (size_t)r * D_ + c4 * 4)
                                  : (e + (size_t)r * D_ + (c4 - 128) * 4);
    *(float4*)(X + (size_t)r * (2 * D_) + c4 * 4) = *(const float4*)src;
}

// ---------------------------------------------------------------------------
// SGEMM: C[M,N] = A[M,K] @ W[K,N] + bias.   128x128x8 tile, 256 thr, 8x8/thr.
// MODE 0: C row-major [M,N].  MODE 1: head-split scatter to [B,H,S,HD] (N=512).
// Requires M%128==0, N%128==0, K%8==0 (true for all calls here).
// ---------------------------------------------------------------------------
template <int MODE>
__global__ __launch_bounds__(256) void sgemm_kernel(
    const float* __restrict__ A, const float* __restrict__ W,
    const float* __restrict__ bias, float* __restrict__ C,
    int N, int K)
{
    __shared__ float As[8][128];
    __shared__ float Bs[8][128];

    const int tid = threadIdx.x;
    const int bn = blockIdx.x, bm = blockIdx.y;
    const int ty = tid >> 4, tx = tid & 15;

    const float* Ap = A + (size_t)(bm * 128) * K;
    const float* Wp = W + bn * 128;

    float acc[8][8];
#pragma unroll
    for (int i = 0; i < 8; i++)
#pragma unroll
        for (int j = 0; j < 8; j++) acc[i][j] = 0.f;

    const int arow = tid >> 1,  ac = (tid & 1) * 4;
    const int brow = tid >> 5,  bc = (tid & 31) * 4;

    for (int k0 = 0; k0 < K; k0 += 8) {
        float4 a = *(const float4*)(Ap + (size_t)arow * K + k0 + ac);
        As[ac + 0][arow] = a.x;
        As[ac + 1][arow] = a.y;
        As[ac + 2][arow] = a.z;
        As[ac + 3][arow] = a.w;
        *(float4*)(&Bs[brow][bc]) =
            *(const float4*)(Wp + (size_t)(k0 + brow) * N + bc);
        __syncthreads();

#pragma unroll
        for (int kk = 0; kk < 8; kk++) {
            float ra[8], rb[8];
            *(float4*)(ra)     = *(const float4*)(&As[kk][ty * 8]);
            *(float4*)(ra + 4) = *(const float4*)(&As[kk][ty * 8 + 4]);
            *(float4*)(rb)     = *(const float4*)(&Bs[kk][tx * 8]);
            *(float4*)(rb + 4) = *(const float4*)(&Bs[kk][tx * 8 + 4]);
#pragma unroll
            for (int i = 0; i < 8; i++)
#pragma unroll
                for (int j = 0; j < 8; j++)
                    acc[i][j] = fmaf(ra[i], rb[j], acc[i][j]);
        }
        __syncthreads();
    }

#pragma unroll
    for (int i = 0; i < 8; i++) {
        int r = bm * 128 + ty * 8 + i;
#pragma unroll
        for (int jj = 0; jj < 8; jj += 4) {
            int n = bn * 128 + tx * 8 + jj;
            float4 v;
            v.x = acc[i][jj + 0] + bias[n + 0];
            v.y = acc[i][jj + 1] + bias[n + 1];
            v.z = acc[i][jj + 2] + bias[n + 2];
            v.w = acc[i][jj + 3] + bias[n + 3];
            if (MODE == 0) {
                *(float4*)(C + (size_t)r * N + n) = v;
            } else {
                int bb = r >> 11, ss = r & (S_ - 1);
                int hh = n >> 6,  dd = n & (HD_ - 1);
                *(float4*)(C + (((size_t)bb * H_ + hh) * S_ + ss) * HD_ + dd) = v;
            }
        }
    }
}

// ---------------------------------------------------------------------------
// Flash attention with masked-softmax + L1 renorm.
//   s'  = (q.k) * scale * M
//   p_j = exp(s'_j - m) * M_j ;  Z = sum exp(s'_j - m)
//   out = (sum p_j V_j) / (sum p_j + EPS * Z)
// Block = 64 q-rows x one (b,h). 256 threads, 4x4 microtile.
// smem: qs[64][68], kst[64(d)][68(j)] (aliased by p-tile [64(r)][68(j)]),
//       vs[64][68], ms[64][68]  -> 69632 B dynamic.
// ---------------------------------------------------------------------------
#define SMS 68
#define ATTN_SMEM (4 * 64 * SMS * 4)

__global__ __launch_bounds__(256) void attn_kernel(
    const float* __restrict__ Q, const float* __restrict__ K,
    const float* __restrict__ V, const float* __restrict__ Mm,
    float* __restrict__ Out)
{
    extern __shared__ float sm[];
    float* qs  = sm;                 // [64][SMS] q rows, d cols
    float* kst = sm + 64 * SMS;      // [64][SMS] d rows, j cols (transposed K)
    float* ps  = kst;                // alias: p tile [64][SMS] r rows, j cols
    float* vs  = sm + 2 * 64 * SMS;  // [64][SMS] j rows, d cols
    float* ms  = sm + 3 * 64 * SMS;  // [64][SMS] r rows, j cols

    const int q0 = blockIdx.x * 64;
    const int h  = blockIdx.y;
    const int b  = blockIdx.z;
    const int tid = threadIdx.x;
    const int r4 = (tid >> 4) * 4;      // base of 4 q-rows
    const int c0 = (tid & 15) * 4;      // base of 4 cols (k-index / out-dim)

    const size_t bh = (size_t)b * H_ + h;
    const float* Qp = Q + bh * S_ * HD_;
    const float* Kp = K + bh * S_ * HD_;
    const float* Vp = V + bh * S_ * HD_;
    const float* Mp = Mm + (size_t)b * S_ * S_;
    const float scale = 0.125f;  // HD^-0.5

    // load Q tile
#pragma unroll
    for (int i = 0; i < 4; i++) {
        int f = tid + 256 * i;
        int row = f >> 4, cc = (f & 15) * 4;
        *(float4*)(qs + row * SMS + cc) =
            *(const float4*)(Qp + (size_t)(q0 + row) * HD_ + cc);
    }

    float mrow[4], Zp[4], Tp[4], acc[4][4];
#pragma unroll
    for (int i = 0; i < 4; i++) {
        mrow[i] = -1e30f; Zp[i] = 0.f; Tp[i] = 0.f;
#pragma unroll
        for (int j = 0; j < 4; j++) acc[i][j] = 0.f;
    }
    __syncthreads();

    for (int k0t = 0; k0t < S_; k0t += 64) {
        // load K (transposed), V, M tiles
#pragma unroll
        for (int i = 0; i < 4; i++) {
            int f = tid + 256 * i;
            int row = f >> 4, cc = (f & 15) * 4;
            float4 kv = *(const float4*)(Kp + (size_t)(k0t + row) * HD_ + cc);
            kst[(cc + 0) * SMS + row] = kv.x;
            kst[(cc + 1) * SMS + row] = kv.y;
            kst[(cc + 2) * SMS + row] = kv.z;
            kst[(cc + 3) * SMS + row] = kv.w;
            *(float4*)(vs + row * SMS + cc) =
                *(const float4*)(Vp + (size_t)(k0t + row) * HD_ + cc);
            *(float4*)(ms + row * SMS + cc) =
                *(const float4*)(Mp + (size_t)(q0 + row) * S_ + k0t + cc);
        }
        __syncthreads();

        // scores: s[i][j] = q[r4+i] . k[c0+j]
        float s[4][4];
#pragma unroll
        for (int i = 0; i < 4; i++)
#pragma unroll
            for (int j = 0; j < 4; j++) s[i][j] = 0.f;

#pragma unroll
        for (int d = 0; d < HD_; d += 4) {
            float4 kv0 = *(const float4*)(kst + (d + 0) * SMS + c0);
            float4 kv1 = *(const float4*)(kst + (d + 1) * SMS + c0);
            float4 kv2 = *(const float4*)(kst + (d + 2) * SMS + c0);
            float4 kv3 = *(const float4*)(kst + (d + 3) * SMS + c0);
#pragma unroll
            for (int i = 0; i < 4; i++) {
                float4 qv = *(const float4*)(qs + (r4 + i) * SMS + d);
                s[i][0] = fmaf(qv.x, kv0.x, s[i][0]);
                s[i][0] = fmaf(qv.y, kv1.x, s[i][0]);
                s[i][0] = fmaf(qv.z, kv2.x, s[i][0]);
                s[i][0] = fmaf(qv.w, kv3.x, s[i][0]);
                s[i][1] = fmaf(qv.x, kv0.y, s[i][1]);
                s[i][1] = fmaf(qv.y, kv1.y, s[i][1]);
                s[i][1] = fmaf(qv.z, kv2.y, s[i][1]);
                s[i][1] = fmaf(qv.w, kv3.y, s[i][1]);
                s[i][2] = fmaf(qv.x, kv0.z, s[i][2]);
                s[i][2] = fmaf(qv.y, kv1.z, s[i][2]);
                s[i][2] = fmaf(qv.z, kv2.z, s[i][2]);
                s[i][2] = fmaf(qv.w, kv3.z, s[i][2]);
                s[i][3] = fmaf(qv.x, kv0.w, s[i][3]);
                s[i][3] = fmaf(qv.y, kv1.w, s[i][3]);
                s[i][3] = fmaf(qv.z, kv2.w, s[i][3]);
                s[i][3] = fmaf(qv.w, kv3.w, s[i][3]);
            }
        }

        // mask * scale (mask applied BEFORE softmax, per reference)
        float4 mv[4];
#pragma unroll
        for (int i = 0; i < 4; i++) {
            mv[i] = *(const float4*)(ms + (r4 + i) * SMS + c0);
            s[i][0] *= scale * mv[i].x;
            s[i][1] *= scale * mv[i].y;
            s[i][2] *= scale * mv[i].z;
            s[i][3] *= scale * mv[i].w;
        }

        __syncthreads();  // all kst reads done before p-tile overwrite

        // online softmax update (rows owned by 16-lane groups)
#pragma unroll
        for (int i = 0; i < 4; i++) {
            float bm = fmaxf(fmaxf(s[i][0], s[i][1]), fmaxf(s[i][2], s[i][3]));
#pragma unroll
            for (int o = 8; o; o >>= 1)
                bm = fmaxf(bm, __shfl_xor_sync(0xffffffffu, bm, o));
            float nm  = fmaxf(mrow[i], bm);
            float fsc = __expf(mrow[i] - nm);
            mrow[i] = nm;
            Zp[i] *= fsc; Tp[i] *= fsc;
            acc[i][0] *= fsc; acc[i][1] *= fsc;
            acc[i][2] *= fsc; acc[i][3] *= fsc;

            float e0 = __expf(s[i][0] - nm);
            float e1 = __expf(s[i][1] - nm);
            float e2 = __expf(s[i][2] - nm);
            float e3 = __expf(s[i][3] - nm);
            Zp[i] += (e0 + e1) + (e2 + e3);
            float p0 = e0 * mv[i].x, p1 = e1 * mv[i].y;
            float p2 = e2 * mv[i].z, p3 = e3 * mv[i].w;
            Tp[i] += (p0 + p1) + (p2 + p3);
            *(float4*)(ps + (r4 + i) * SMS + c0) = make_float4(p0, p1, p2, p3);
        }
        __syncthreads();  // p tile visible

        // acc += P @ V   (thread: 4 rows x 4 out-dims at c0)
#pragma unroll
        for (int j = 0; j < 64; j += 4) {
            float4 vv0 = *(const float4*)(vs + (j + 0) * SMS + c0);
            float4 vv1 = *(const float4*)(vs + (j + 1) * SMS + c0);
            float4 vv2 = *(const float4*)(vs + (j + 2) * SMS + c0);
            float4 vv3 = *(const float4*)(vs + (j + 3) * SMS + c0);
#pragma unroll
            for (int i = 0; i < 4; i++) {
                float4 pv = *(const float4*)(ps + (r4 + i) * SMS + j);
                acc[i][0] = fmaf(pv.x, vv0.x, acc[i][0]);
                acc[i][0] = fmaf(pv.y, vv1.x, acc[i][0]);
                acc[i][0] = fmaf(pv.z, vv2.x, acc[i][0]);
                acc[i][0] = fmaf(pv.w, vv3.x, acc[i][0]);
                acc[i][1] = fmaf(pv.x, vv0.y, acc[i][1]);
                acc[i][1] = fmaf(pv.y, vv1.y, acc[i][1]);
                acc[i][1] = fmaf(pv.z, vv2.y, acc[i][1]);
                acc[i][1] = fmaf(pv.w, vv3.y, acc[i][1]);
                acc[i][2] = fmaf(pv.x, vv0.z, acc[i][2]);
                acc[i][2] = fmaf(pv.y, vv1.z, acc[i][2]);
                acc[i][2] = fmaf(pv.z, vv2.z, acc[i][2]);
                acc[i][2] = fmaf(pv.w, vv3.z, acc[i][2]);
                acc[i][3] = fmaf(pv.x, vv0.w, acc[i][3]);
                acc[i][3] = fmaf(pv.y, vv1.w, acc[i][3]);
                acc[i][3] = fmaf(pv.z, vv2.w, acc[i][3]);
                acc[i][3] = fmaf(pv.w, vv3.w, acc[i][3]);
            }
        }
        __syncthreads();  // done with p/v tiles before next load
    }

    // finalize: out = acc / (T + EPS * Z); write [B,S,D] merged-head layout
#pragma unroll
    for (int i = 0; i < 4; i++) {
        float Zt = Zp[i], Tt = Tp[i];
#pragma unroll
        for (int o = 8; o; o >>= 1) {
            Zt += __shfl_xor_sync(0xffffffffu, Zt, o);
            Tt += __shfl_xor_sync(0xffffffffu, Tt, o);
        }
        float inv = 1.0f / (Tt + EPS_ * Zt);
        int row = q0 + r4 + i;
        float4 o4 = make_float4(acc[i][0] * inv, acc[i][1] * inv,
                                acc[i][2] * inv, acc[i][3] * inv);
        *(float4*)(Out + ((size_t)b * S_ + row) * D_ + h * HD_ + c0) = o4;
    }
}

// ---------------------------------------------------------------------------
// Host
// ---------------------------------------------------------------------------
extern "C" void kernel_launch(void* const* d_in, const int* in_sizes, int n_in,
                              void* d_out, int out_size)
{
    const float* gene = (const float*)d_in[0];
    const float* expr = (const float*)d_in[1];
    const float* Mm   = (const float*)d_in[2];
    const float* Wf   = (const float*)d_in[3];
    const float* bf   = (const float*)d_in[4];
    const float* Wq   = (const float*)d_in[5];
    const float* bq   = (const float*)d_in[6];
    const float* Wk   = (const float*)d_in[7];
    const float* bk   = (const float*)d_in[8];
    const float* Wv   = (const float*)d_in[9];
    const float* bv   = (const float*)d_in[10];
    const float* Wo   = (const float*)d_in[11];
    const float* bo   = (const float*)d_in[12];
    float* out = (float*)d_out;

    float *X, *fused, *Qb, *Kb, *Vb, *Ab;
    cudaGetSymbolAddress((void**)&X,     g_X);
    cudaGetSymbolAddress((void**)&fused, g_fused);
    cudaGetSymbolAddress((void**)&Qb,    g_Q);
    cudaGetSymbolAddress((void**)&Kb,    g_K);
    cudaGetSymbolAddress((void**)&Vb,    g_V);
    cudaGetSymbolAddress((void**)&Ab,    g_attn);

    cudaFuncSetAttribute(attn_kernel,
                         cudaFuncAttributeMaxDynamicSharedMemorySize,
                         ATTN_SMEM);

    // 1. concat
    cat_kernel<<<ROWS_, 256>>>(gene, expr, X);

    // 2. fused projection  (M=8192, K=1024, N=512)
    sgemm_kernel<0><<<dim3(D_ / 128, ROWS_ / 128), 256>>>(X, Wf, bf, fused,
                                                          D_, 2 * D_);
    // 3. Q, K, V projections with head-split epilogue
    sgemm_kernel<1><<<dim3(D_ / 128, ROWS_ / 128), 256>>>(fused, Wq, bq, Qb,
                                                          D_, D_);
    sgemm_kernel<1><<<dim3(D_ / 128, ROWS_ / 128), 256>>>(fused, Wk, bk, Kb,
                                                          D_, D_);
    sgemm_kernel<1><<<dim3(D_ / 128, ROWS_ / 128), 256>>>(expr, Wv, bv, Vb,
                                                          D_, D_);

    // 4. fused masked-softmax flash attention
    attn_kernel<<<dim3(S_ / 64, H_, B_), 256, ATTN_SMEM>>>(Qb, Kb, Vb, Mm, Ab);

    // 5. output projection
    sgemm_kernel<0><<<dim3(D_ / 128, ROWS_ / 128), 256>>>(Ab, Wo, bo, out,
                                                          D_, D_);
}

// round 6
// speedup vs baseline: 1.7085x; 1.7085x over previous
#include <cuda_runtime.h>
#include <cuda_bf16.h>
#include <stdint.h>

#define B_   4
#define S_   2048
#define D_   512
#define H_   8
#define HD_  64
#define ROWS_ (B_ * S_)          // 8192
#define EPS_ 1e-8f

// ---------------------------------------------------------------------------
// Scratch (__device__ globals; allocations are forbidden)
// ---------------------------------------------------------------------------
__device__ float g_fused[(size_t)ROWS_ * D_];
__device__ float g_Q    [(size_t)ROWS_ * D_];   // [B,H,S,HD]
__device__ float g_K    [(size_t)ROWS_ * D_];   // [B,H,S,HD]
__device__ float g_V    [(size_t)ROWS_ * D_];   // [B,H,S,HD]
__device__ float g_attn [(size_t)ROWS_ * D_];   // [B,S,D]
// Weights transposed to [N][K], split bf16 hi/lo
__device__ unsigned short g_Wf_h[(size_t)D_ * 2 * D_];
__device__ unsigned short g_Wf_l[(size_t)D_ * 2 * D_];
__device__ unsigned short g_Wq_h[(size_t)D_ * D_];
__device__ unsigned short g_Wq_l[(size_t)D_ * D_];
__device__ unsigned short g_Wk_h[(size_t)D_ * D_];
__device__ unsigned short g_Wk_l[(size_t)D_ * D_];
__device__ unsigned short g_Wv_h[(size_t)D_ * D_];
__device__ unsigned short g_Wv_l[(size_t)D_ * D_];
__device__ unsigned short g_Wo_h[(size_t)D_ * D_];
__device__ unsigned short g_Wo_l[(size_t)D_ * D_];

// ---------------------------------------------------------------------------
// sm_80-level PTX helpers (NO tcgen05 — target is plain sm_103)
// ---------------------------------------------------------------------------
__device__ __forceinline__ uint32_t smem_u32(const void* p) {
    uint32_t a;
    asm("{ .reg .u64 t; cvta.to.shared.u64 t, %1; cvt.u32.u64 %0, t; }"
        : "=r"(a) : "l"(p));
    return a;
}
__device__ __forceinline__ void ldm4(uint32_t addr, uint32_t* r) {
    asm volatile("ldmatrix.sync.aligned.m8n8.x4.shared.b16 {%0,%1,%2,%3}, [%4];"
                 : "=r"(r[0]), "=r"(r[1]), "=r"(r[2]), "=r"(r[3]) : "r"(addr));
}
__device__ __forceinline__ void mma_bf16(float* c, const uint32_t* a,
                                         const uint32_t* b) {
    asm volatile("mma.sync.aligned.m16n8k16.row.col.f32.bf16.bf16.f32 "
                 "{%0,%1,%2,%3}, {%4,%5,%6,%7}, {%8,%9}, {%0,%1,%2,%3};"
                 : "+f"(c[0]), "+f"(c[1]), "+f"(c[2]), "+f"(c[3])
                 : "r"(a[0]), "r"(a[1]), "r"(a[2]), "r"(a[3]),
                   "r"(b[0]), "r"(b[1]));
}
#define CP_ASYNC16(dst, src) \
    asm volatile("cp.async.ca.shared.global [%0], [%1], 16;" \
                 :: "r"(dst), "l"(src))
#define CP_COMMIT() asm volatile("cp.async.commit_group;" ::: "memory")
#define CP_WAIT0()  asm volatile("cp.async.wait_group 0;" ::: "memory")
#define CP_WAIT1()  asm volatile("cp.async.wait_group 1;" ::: "memory")

__device__ __forceinline__ void bsplit(float v, unsigned short& h,
                                       unsigned short& l) {
    __nv_bfloat16 hb = __float2bfloat16(v);
    float r = v - __bfloat162float(hb);
    __nv_bfloat16 lb = __float2bfloat16(r);
    h = __bfloat16_as_ushort(hb);
    l = __bfloat16_as_ushort(lb);
}

// ---------------------------------------------------------------------------
// Weight preconvert: W[K][N] row-major -> Wt[N][K] bf16 hi/lo
// ---------------------------------------------------------------------------
__global__ void wconv_kernel(const float* __restrict__ W,
                             unsigned short* __restrict__ Th,
                             unsigned short* __restrict__ Tl,
                             int K, int N)
{
    __shared__ float t[32][33];
    int tx = threadIdx.x, ty = threadIdx.y;
    int k0 = blockIdx.y * 32, n0 = blockIdx.x * 32;
    t[ty][tx] = W[(size_t)(k0 + ty) * N + n0 + tx];
    __syncthreads();
    float v = t[tx][ty];                 // W[k0+tx][n0+ty]
    unsigned short h, l;
    bsplit(v, h, l);
    size_t o = (size_t)(n0 + ty) * K + k0 + tx;
    Th[o] = h;
    Tl[o] = l;
}

// ---------------------------------------------------------------------------
// 3xBF16 tensor-core GEMM: C[M,N] = A[M,K] @ W[K,N] + bias
//   A fp32 (split source at Ksplit); W pre-split bf16 hi/lo [N][K].
// CTA 128x128, K-chunk 32, 8 warps (2x4) of 64x32, 2-stage pipeline.
// smem rows padded to 40 bf16 (80 B) -> conflict-free ldmatrix.
// MODE 0: row-major C.  MODE 1: head-split scatter to [B,H,S,HD].
// ---------------------------------------------------------------------------
#define GSTAGE   40960
#define GOFF_AH  0
#define GOFF_AL  10240
#define GOFF_BH  20480
#define GOFF_BL  30720
#define GM_SMEM  (2 * GSTAGE)

__device__ __forceinline__ void gemm_ldA(const float* A0, const float* A1,
                                         int sA0, int sA1, int Ksplit,
                                         int bm, int k0, int tid, float4* av)
{
#pragma unroll
    for (int i = 0; i < 4; i++) {
        int fid = tid + i * 256;
        int m = fid >> 3, kq = fid & 7;
        int kg = k0 + kq * 4;
        const float* src = (kg < Ksplit)
            ? A0 + (size_t)(bm + m) * sA0 + kg
            : A1 + (size_t)(bm + m) * sA1 + (kg - Ksplit);
        av[i] = *(const float4*)src;
    }
}
__device__ __forceinline__ void gemm_stA(unsigned char* stage, int tid,
                                         const float4* av)
{
#pragma unroll
    for (int i = 0; i < 4; i++) {
        int fid = tid + i * 256;
        int m = fid >> 3, kq = fid & 7;
        ushort4 h, l;
        bsplit(av[i].x, h.x, l.x);
        bsplit(av[i].y, h.y, l.y);
        bsplit(av[i].z, h.z, l.z);
        bsplit(av[i].w, h.w, l.w);
        *(ushort4*)(stage + GOFF_AH + m * 80 + kq * 8) = h;
        *(ushort4*)(stage + GOFF_AL + m * 80 + kq * 8) = l;
    }
}
__device__ __forceinline__ void gemm_cpB(uint32_t stage_u32,
                                         const unsigned short* Bh,
                                         const unsigned short* Bl,
                                         int bn, int K, int k0, int tid)
{
#pragma unroll
    for (int i = 0; i < 2; i++) {
        int fid = tid + i * 256;
        int n = fid >> 2, c16 = fid & 3;
        size_t gs = (size_t)(bn + n) * K + k0 + c16 * 8;
        CP_ASYNC16(stage_u32 + GOFF_BH + n * 80 + c16 * 16, (const char*)(Bh + gs));
        CP_ASYNC16(stage_u32 + GOFF_BL + n * 80 + c16 * 16, (const char*)(Bl + gs));
    }
}

template <int MODE>
__global__ __launch_bounds__(256) void mm_mma(
    const float* __restrict__ A0, const float* __restrict__ A1,
    int sA0, int sA1, int Ksplit,
    const unsigned short* __restrict__ Bh, const unsigned short* __restrict__ Bl,
    const float* __restrict__ bias, float* __restrict__ C,
    int N, int K)
{
    extern __shared__ __align__(16) unsigned char smem[];
    const uint32_t sb = smem_u32(smem);
    const int tid = threadIdx.x, lane = tid & 31, wid = tid >> 5;
    const int wy = wid >> 2, wx = wid & 3;
    const int bn = blockIdx.x * 128, bm = blockIdx.y * 128;
    const int NC = K / 32;

    float acc[4][4][4];
#pragma unroll
    for (int i = 0; i < 4; i++)
#pragma unroll
        for (int j = 0; j < 4; j++)
#pragma unroll
            for (int q = 0; q < 4; q++) acc[i][j][q] = 0.f;

    const uint32_t arow = (wy * 64 + (lane & 15)) * 80 + (lane >> 4) * 16;
    const uint32_t brow = (wx * 32 + (lane & 15)) * 80 + (lane >> 4) * 16;

    float4 av[4];
    gemm_ldA(A0, A1, sA0, sA1, Ksplit, bm, 0, tid, av);
    gemm_cpB(sb, Bh, Bl, bn, K, 0, tid);
    CP_COMMIT();
    gemm_stA(smem, tid, av);

    for (int c = 0; c < NC; c++) {
        const int st = c & 1;
        const bool more = (c + 1 < NC);
        if (more) {
            gemm_ldA(A0, A1, sA0, sA1, Ksplit, bm, (c + 1) * 32, tid, av);
            gemm_cpB(sb + ((c + 1) & 1) * GSTAGE, Bh, Bl, bn, K, (c + 1) * 32, tid);
            CP_COMMIT();
        }
        if (more) { CP_WAIT1(); } else { CP_WAIT0(); }
        __syncthreads();

        const uint32_t s0 = sb + st * GSTAGE;
#pragma unroll
        for (int ks = 0; ks < 2; ks++) {
            uint32_t ah[4][4], al[4][4];
#pragma unroll
            for (int mt = 0; mt < 4; mt++) {
                ldm4(s0 + GOFF_AH + arow + mt * 1280 + ks * 32, ah[mt]);
                ldm4(s0 + GOFF_AL + arow + mt * 1280 + ks * 32, al[mt]);
            }
#pragma unroll
            for (int nb = 0; nb < 2; nb++) {
                uint32_t bh4[4], bl4[4];
                ldm4(s0 + GOFF_BH + brow + nb * 1280 + ks * 32, bh4);
                ldm4(s0 + GOFF_BL + brow + nb * 1280 + ks * 32, bl4);
                uint32_t th0[2] = {bh4[0], bh4[2]}, th1[2] = {bh4[1], bh4[3]};
                uint32_t tl0[2] = {bl4[0], bl4[2]}, tl1[2] = {bl4[1], bl4[3]};
#pragma unroll
                for (int mt = 0; mt < 4; mt++) {
                    mma_bf16(acc[mt][2 * nb],     ah[mt], th0);
                    mma_bf16(acc[mt][2 * nb + 1], ah[mt], th1);
                    mma_bf16(acc[mt][2 * nb],     ah[mt], tl0);
                    mma_bf16(acc[mt][2 * nb + 1], ah[mt], tl1);
                    mma_bf16(acc[mt][2 * nb],     al[mt], th0);
                    mma_bf16(acc[mt][2 * nb + 1], al[mt], th1);
                }
            }
        }
        if (more) gemm_stA(smem + ((c + 1) & 1) * GSTAGE, tid, av);
        __syncthreads();
    }

    // epilogue
#pragma unroll
    for (int mt = 0; mt < 4; mt++) {
#pragma unroll
        for (int nt = 0; nt < 4; nt++) {
            int r0 = bm + wy * 64 + mt * 16 + (lane >> 2);
            int col = bn + wx * 32 + nt * 8 + 2 * (lane & 3);
            float b0 = bias[col], b1 = bias[col + 1];
            float2 v0 = make_float2(acc[mt][nt][0] + b0, acc[mt][nt][1] + b1);
            float2 v1 = make_float2(acc[mt][nt][2] + b0, acc[mt][nt][3] + b1);
            if (MODE == 0) {
                *(float2*)(C + (size_t)r0 * N + col) = v0;
                *(float2*)(C + (size_t)(r0 + 8) * N + col) = v1;
            } else {
                int hh = col >> 6, dd = col & (HD_ - 1);
                int bb0 = r0 >> 11, ss0 = r0 & (S_ - 1);
                *(float2*)(C + (((size_t)bb0 * H_ + hh) * S_ + ss0) * HD_ + dd) = v0;
                int r1 = r0 + 8;
                int bb1 = r1 >> 11, ss1 = r1 & (S_ - 1);
                *(float2*)(C + (((size_t)bb1 * H_ + hh) * S_ + ss1) * HD_ + dd) = v1;
            }
        }
    }
}

// ---------------------------------------------------------------------------
// Tensor-core flash attention with masked softmax + L1 renorm.
// CTA: 128 q-rows x one (b,h); 8 warps x 16 rows; 64-key blocks.
// QK^T: 3xBF16 (Qhi/Qlo smem, Khi/Klo smem). PV: P split hi/lo in regs
// (S-accum frag == A frag layout), V transposed hi/lo in smem.
//   p = exp(s'-m)*M; Z=sum exp; T=sum p; out = (sum p*V)/(T + EPS*Z)
// ---------------------------------------------------------------------------
#define OQH 0
#define OQL 18432
#define OKH 36864
#define OKL 46080
#define OVH 55296
#define OVL 64512
#define OMS 73728
#define ATTN_SMEM (73728 + 34816)   // 108544

__global__ __launch_bounds__(256) void attn_mma(
    const float* __restrict__ Q, const float* __restrict__ K,
    const float* __restrict__ V, const float* __restrict__ Mm,
    float* __restrict__ Out)
{
    extern __shared__ __align__(16) unsigned char smem[];
    const uint32_t sb = smem_u32(smem);

    const int q0 = blockIdx.x * 128;
    const int h  = blockIdx.y;
    const int b  = blockIdx.z;
    const int tid = threadIdx.x, lane = tid & 31, w = tid >> 5;
    const int qr = lane >> 2, qc = lane & 3;

    const size_t bh = (size_t)b * H_ + h;
    const float* Qp = Q + bh * S_ * HD_;
    const float* Kp = K + bh * S_ * HD_;
    const float* Vp = V + bh * S_ * HD_;
    const float* Mp = Mm + (size_t)b * S_ * S_;

    // ---- load Q tile (128x64), split to bf16 hi/lo ----
#pragma unroll
    for (int i = 0; i < 8; i++) {
        int fid = tid + i * 256;
        int row = fid >> 4, c4 = (fid & 15) * 4;
        float4 v = *(const float4*)(Qp + (size_t)(q0 + row) * HD_ + c4);
        ushort4 hh, ll;
        bsplit(v.x, hh.x, ll.x); bsplit(v.y, hh.y, ll.y);
        bsplit(v.z, hh.z, ll.z); bsplit(v.w, hh.w, ll.w);
        *(ushort4*)(smem + OQH + row * 144 + c4 * 2) = hh;
        *(ushort4*)(smem + OQL + row * 144 + c4 * 2) = ll;
    }

    float O[8][4];
#pragma unroll
    for (int t = 0; t < 8; t++)
#pragma unroll
        for (int j = 0; j < 4; j++) O[t][j] = 0.f;
    float m0 = -1e30f, m1 = -1e30f, Z0 = 0.f, Z1 = 0.f, T0 = 0.f, T1 = 0.f;

    const uint32_t qrow = (w * 16 + (lane & 15)) * 144 + (lane >> 4) * 16;
    const uint32_t klrow = ((lane & 15)) * 144 + (lane >> 4) * 16;

    for (int kb = 0; kb < S_ / 64; kb++) {
        const int kk0 = kb * 64;
        // M tile via cp.async (128 x 64 f32, pad stride 272B)
#pragma unroll
        for (int i = 0; i < 8; i++) {
            int fid = tid + i * 256;
            int row = fid >> 4, c16 = fid & 15;
            CP_ASYNC16(sb + OMS + row * 272 + c16 * 16,
                       (const char*)(Mp + (size_t)(q0 + row) * S_ + kk0 + c16 * 4));
        }
        CP_COMMIT();
        // K (64x64) -> Khi/Klo ; V -> transposed Vthi/Vtlo [d][key]
#pragma unroll
        for (int i = 0; i < 4; i++) {
            int fid = tid + i * 256;
            int row = fid >> 4, c4 = (fid & 15) * 4;
            float4 kv = *(const float4*)(Kp + (size_t)(kk0 + row) * HD_ + c4);
            float4 vv = *(const float4*)(Vp + (size_t)(kk0 + row) * HD_ + c4);
            ushort4 kh, kl;
            bsplit(kv.x, kh.x, kl.x); bsplit(kv.y, kh.y, kl.y);
            bsplit(kv.z, kh.z, kl.z); bsplit(kv.w, kh.w, kl.w);
            *(ushort4*)(smem + OKH + row * 144 + c4 * 2) = kh;
            *(ushort4*)(smem + OKL + row * 144 + c4 * 2) = kl;
            unsigned short vh, vl;
            bsplit(vv.x, vh, vl);
            *(unsigned short*)(smem + OVH + (c4 + 0) * 144 + row * 2) = vh;
            *(unsigned short*)(smem + OVL + (c4 + 0) * 144 + row * 2) = vl;
            bsplit(vv.y, vh, vl);
            *(unsigned short*)(smem + OVH + (c4 + 1) * 144 + row * 2) = vh;
            *(unsigned short*)(smem + OVL + (c4 + 1) * 144 + row * 2) = vl;
            bsplit(vv.z, vh, vl);
            *(unsigned short*)(smem + OVH + (c4 + 2) * 144 + row * 2) = vh;
            *(unsigned short*)(smem + OVL + (c4 + 2) * 144 + row * 2) = vl;
            bsplit(vv.w, vh, vl);
            *(unsigned short*)(smem + OVH + (c4 + 3) * 144 + row * 2) = vh;
            *(unsigned short*)(smem + OVL + (c4 + 3) * 144 + row * 2) = vl;
        }
        CP_WAIT0();
        __syncthreads();

        // ---- S = Q K^T (3xBF16) ----
        float S[8][4];
#pragma unroll
        for (int t = 0; t < 8; t++)
#pragma unroll
            for (int j = 0; j < 4; j++) S[t][j] = 0.f;
#pragma unroll
        for (int ks = 0; ks < 4; ks++) {
            uint32_t ah[4], al[4];
            ldm4(sb + OQH + qrow + ks * 32, ah);
            ldm4(sb + OQL + qrow + ks * 32, al);
#pragma unroll
            for (int nb = 0; nb < 4; nb++) {
                uint32_t bh4[4], bl4[4];
                ldm4(sb + OKH + klrow + nb * 2304 + ks * 32, bh4);
                ldm4(sb + OKL + klrow + nb * 2304 + ks * 32, bl4);
                uint32_t th0[2] = {bh4[0], bh4[2]}, th1[2] = {bh4[1], bh4[3]};
                uint32_t tl0[2] = {bl4[0], bl4[2]}, tl1[2] = {bl4[1], bl4[3]};
                mma_bf16(S[2 * nb],     ah, th0);
                mma_bf16(S[2 * nb + 1], ah, th1);
                mma_bf16(S[2 * nb],     ah, tl0);
                mma_bf16(S[2 * nb + 1], ah, tl1);
                mma_bf16(S[2 * nb],     al, th0);
                mma_bf16(S[2 * nb + 1], al, th1);
            }
        }

        // ---- masked scale + online softmax ----
        const unsigned char* msp = smem + OMS;
        const int mr0 = (w * 16 + qr) * 272 + qc * 8;
        float bm0 = -1e30f, bm1 = -1e30f;
        float mva[8], mvb[8], mvc[8], mvd[8];
#pragma unroll
        for (int t = 0; t < 8; t++) {
            float2 ma = *(const float2*)(msp + mr0 + t * 32);
            float2 mb = *(const float2*)(msp + mr0 + 8 * 272 + t * 32);
            mva[t] = ma.x; mvb[t] = ma.y; mvc[t] = mb.x; mvd[t] = mb.y;
            S[t][0] *= 0.125f * ma.x;
            S[t][1] *= 0.125f * ma.y;
            S[t][2] *= 0.125f * mb.x;
            S[t][3] *= 0.125f * mb.y;
            bm0 = fmaxf(bm0, fmaxf(S[t][0], S[t][1]));
            bm1 = fmaxf(bm1, fmaxf(S[t][2], S[t][3]));
        }
        bm0 = fmaxf(bm0, __shfl_xor_sync(0xffffffffu, bm0, 1));
        bm0 = fmaxf(bm0, __shfl_xor_sync(0xffffffffu, bm0, 2));
        bm1 = fmaxf(bm1, __shfl_xor_sync(0xffffffffu, bm1, 1));
        bm1 = fmaxf(bm1, __shfl_xor_sync(0xffffffffu, bm1, 2));
        float nm0 = fmaxf(m0, bm0), nm1 = fmaxf(m1, bm1);
        float f0 = __expf(m0 - nm0), f1 = __expf(m1 - nm1);
        m0 = nm0; m1 = nm1;
        Z0 *= f0; Z1 *= f1; T0 *= f0; T1 *= f1;
#pragma unroll
        for (int t = 0; t < 8; t++) {
            O[t][0] *= f0; O[t][1] *= f0; O[t][2] *= f1; O[t][3] *= f1;
            float e0 = __expf(S[t][0] - nm0);
            float e1 = __expf(S[t][1] - nm0);
            float e2 = __expf(S[t][2] - nm1);
            float e3 = __expf(S[t][3] - nm1);
            Z0 += e0 + e1; Z1 += e2 + e3;
            float p0 = e0 * mva[t], p1 = e1 * mvb[t];
            float p2 = e2 * mvc[t], p3 = e3 * mvd[t];
            T0 += p0 + p1; T1 += p2 + p3;
            S[t][0] = p0; S[t][1] = p1; S[t][2] = p2; S[t][3] = p3;
        }

        // ---- pack P to bf16 hi/lo A-fragments ----
        uint32_t phi[4][4], plo[4][4];
#pragma unroll
        for (int kt = 0; kt < 4; kt++) {
            unsigned short h0, l0, h1, l1;
            bsplit(S[2 * kt][0], h0, l0); bsplit(S[2 * kt][1], h1, l1);
            phi[kt][0] = (uint32_t)h0 | ((uint32_t)h1 << 16);
            plo[kt][0] = (uint32_t)l0 | ((uint32_t)l1 << 16);
            bsplit(S[2 * kt][2], h0, l0); bsplit(S[2 * kt][3], h1, l1);
            phi[kt][1] = (uint32_t)h0 | ((uint32_t)h1 << 16);
            plo[kt][1] = (uint32_t)l0 | ((uint32_t)l1 << 16);
            bsplit(S[2 * kt + 1][0], h0, l0); bsplit(S[2 * kt + 1][1], h1, l1);
            phi[kt][2] = (uint32_t)h0 | ((uint32_t)h1 << 16);
            plo[kt][2] = (uint32_t)l0 | ((uint32_t)l1 << 16);
            bsplit(S[2 * kt + 1][2], h0, l0); bsplit(S[2 * kt + 1][3], h1, l1);
            phi[kt][3] = (uint32_t)h0 | ((uint32_t)h1 << 16);
            plo[kt][3] = (uint32_t)l0 | ((uint32_t)l1 << 16);
        }

        // ---- O += P @ V ----
#pragma unroll
        for (int kt = 0; kt < 4; kt++) {
#pragma unroll
            for (int nb = 0; nb < 4; nb++) {
                uint32_t vh4[4], vl4[4];
                ldm4(sb + OVH + klrow + nb * 2304 + kt * 32, vh4);
                ldm4(sb + OVL + klrow + nb * 2304 + kt * 32, vl4);
                uint32_t th0[2] = {vh4[0], vh4[2]}, th1[2] = {vh4[1], vh4[3]};
                uint32_t tl0[2] = {vl4[0], vl4[2]}, tl1[2] = {vl4[1], vl4[3]};
                mma_bf16(O[2 * nb],     phi[kt], th0);
                mma_bf16(O[2 * nb + 1], phi[kt], th1);
                mma_bf16(O[2 * nb],     phi[kt], tl0);
                mma_bf16(O[2 * nb + 1], phi[kt], tl1);
                mma_bf16(O[2 * nb],     plo[kt], th0);
                mma_bf16(O[2 * nb + 1], plo[kt], th1);
            }
        }
        __syncthreads();
    }

    // ---- finalize ----
    T0 += __shfl_xor_sync(0xffffffffu, T0, 1);
    T0 += __shfl_xor_sync(0xffffffffu, T0, 2);
    T1 += __shfl_xor_sync(0xffffffffu, T1, 1);
    T1 += __shfl_xor_sync(0xffffffffu, T1, 2);
    Z0 += __shfl_xor_sync(0xffffffffu, Z0, 1);
    Z0 += __shfl_xor_sync(0xffffffffu, Z0, 2);
    Z1 += __shfl_xor_sync(0xffffffffu, Z1, 1);
    Z1 += __shfl_xor_sync(0xffffffffu, Z1, 2);
    float inv0 = 1.0f / (T0 + EPS_ * Z0);
    float inv1 = 1.0f / (T1 + EPS_ * Z1);

    int gr0 = q0 + w * 16 + qr;
#pragma unroll
    for (int t = 0; t < 8; t++) {
        int d = t * 8 + 2 * qc;
        float2 v0 = make_float2(O[t][0] * inv0, O[t][1] * inv0);
        float2 v1 = make_float2(O[t][2] * inv1, O[t][3] * inv1);
        *(float2*)(Out + ((size_t)b * S_ + gr0) * D_ + h * HD_ + d) = v0;
        *(float2*)(Out + ((size_t)b * S_ + gr0 + 8) * D_ + h * HD_ + d) = v1;
    }
}

// ---------------------------------------------------------------------------
// Host
// ---------------------------------------------------------------------------
extern "C" void kernel_launch(void* const* d_in, const int* in_sizes, int n_in,
                              void* d_out, int out_size)
{
    const float* gene = (const float*)d_in[0];
    const float* expr = (const float*)d_in[1];
    const float* Mm   = (const float*)d_in[2];
    const float* Wf   = (const float*)d_in[3];
    const float* bf   = (const float*)d_in[4];
    const float* Wq   = (const float*)d_in[5];
    const float* bq   = (const float*)d_in[6];
    const float* Wk   = (const float*)d_in[7];
    const float* bk   = (const float*)d_in[8];
    const float* Wv   = (const float*)d_in[9];
    const float* bv   = (const float*)d_in[10];
    const float* Wo   = (const float*)d_in[11];
    const float* bo   = (const float*)d_in[12];
    float* out = (float*)d_out;

    float *fused, *Qb, *Kb, *Vb, *Ab;
    unsigned short *Wfh, *Wfl, *Wqh, *Wql, *Wkh, *Wkl, *Wvh, *Wvl, *Woh, *Wol;
    cudaGetSymbolAddress((void**)&fused, g_fused);
    cudaGetSymbolAddress((void**)&Qb,    g_Q);
    cudaGetSymbolAddress((void**)&Kb,    g_K);
    cudaGetSymbolAddress((void**)&Vb,    g_V);
    cudaGetSymbolAddress((void**)&Ab,    g_attn);
    cudaGetSymbolAddress((void**)&Wfh,   g_Wf_h);
    cudaGetSymbolAddress((void**)&Wfl,   g_Wf_l);
    cudaGetSymbolAddress((void**)&Wqh,   g_Wq_h);
    cudaGetSymbolAddress((void**)&Wql,   g_Wq_l);
    cudaGetSymbolAddress((void**)&Wkh,   g_Wk_h);
    cudaGetSymbolAddress((void**)&Wkl,   g_Wk_l);
    cudaGetSymbolAddress((void**)&Wvh,   g_Wv_h);
    cudaGetSymbolAddress((void**)&Wvl,   g_Wv_l);
    cudaGetSymbolAddress((void**)&Woh,   g_Wo_h);
    cudaGetSymbolAddress((void**)&Wol,   g_Wo_l);

    cudaFuncSetAttribute(mm_mma<0>, cudaFuncAttributeMaxDynamicSharedMemorySize, GM_SMEM);
    cudaFuncSetAttribute(mm_mma<1>, cudaFuncAttributeMaxDynamicSharedMemorySize, GM_SMEM);
    cudaFuncSetAttribute(attn_mma,  cudaFuncAttributeMaxDynamicSharedMemorySize, ATTN_SMEM);

    dim3 wb(32, 32);
    wconv_kernel<<<dim3(D_ / 32, (2 * D_) / 32), wb>>>(Wf, Wfh, Wfl, 2 * D_, D_);
    wconv_kernel<<<dim3(D_ / 32, D_ / 32), wb>>>(Wq, Wqh, Wql, D_, D_);
    wconv_kernel<<<dim3(D_ / 32, D_ / 32), wb>>>(Wk, Wkh, Wkl, D_, D_);
    wconv_kernel<<<dim3(D_ / 32, D_ / 32), wb>>>(Wv, Wvh, Wvl, D_, D_);
    wconv_kernel<<<dim3(D_ / 32, D_ / 32), wb>>>(Wo, Woh, Wol, D_, D_);

    dim3 gg(D_ / 128, ROWS_ / 128);   // (4, 64)

    // fused = concat(gene, expr) @ Wf + bf   (A K-split at 512; no concat pass)
    mm_mma<0><<<gg, 256, GM_SMEM>>>(gene, expr, D_, D_, D_, Wfh, Wfl, bf, fused,
                                    D_, 2 * D_);
    // Q, K from fused; V from expr — head-split epilogue
    mm_mma<1><<<gg, 256, GM_SMEM>>>(fused, fused, D_, D_, D_, Wqh, Wql, bq, Qb,
                                    D_, D_);
    mm_mma<1><<<gg, 256, GM_SMEM>>>(fused, fused, D_, D_, D_, Wkh, Wkl, bk, Kb,
                                    D_, D_);
    mm_mma<1><<<gg, 256, GM_SMEM>>>(expr, expr, D_, D_, D_, Wvh, Wvl, bv, Vb,
                                    D_, D_);

    attn_mma<<<dim3(S_ / 128, H_, B_), 256, ATTN_SMEM>>>(Qb, Kb, Vb, Mm, Ab);

    // out = attn @ Wo + bo
    mm_mma<0><<<gg, 256, GM_SMEM>>>(Ab, Ab, D_, D_, D_, Woh, Wol, bo, out,
                                    D_, D_);
}

// round 7
// speedup vs baseline: 1.9756x; 1.1564x over previous
#include <cuda_runtime.h>
#include <cuda_bf16.h>
#include <stdint.h>

#define B_   4
#define S_   2048
#define D_   512
#define H_   8
#define HD_  64
#define ROWS_ (B_ * S_)          // 8192
#define EPS_ 1e-8f

// ---------------------------------------------------------------------------
// Scratch (__device__ globals; allocations are forbidden)
// ---------------------------------------------------------------------------
__device__ float g_Q    [(size_t)ROWS_ * D_];   // [B,H,S,HD]
__device__ float g_K    [(size_t)ROWS_ * D_];   // [B,H,S,HD]
__device__ float g_V    [(size_t)ROWS_ * D_];   // [B,H,S,HD]
__device__ float g_attn [(size_t)ROWS_ * D_];   // [B,S,D]
// fused activations, pre-split bf16 hi/lo (fp32 copy never needed)
__device__ unsigned short g_fus_h[(size_t)ROWS_ * D_];
__device__ unsigned short g_fus_l[(size_t)ROWS_ * D_];
// Weights transposed to [N][K], split bf16 hi/lo
__device__ unsigned short g_Wf_h[(size_t)D_ * 2 * D_];
__device__ unsigned short g_Wf_l[(size_t)D_ * 2 * D_];
__device__ unsigned short g_Wq_h[(size_t)D_ * D_];
__device__ unsigned short g_Wq_l[(size_t)D_ * D_];
__device__ unsigned short g_Wk_h[(size_t)D_ * D_];
__device__ unsigned short g_Wk_l[(size_t)D_ * D_];
__device__ unsigned short g_Wv_h[(size_t)D_ * D_];
__device__ unsigned short g_Wv_l[(size_t)D_ * D_];
__device__ unsigned short g_Wo_h[(size_t)D_ * D_];
__device__ unsigned short g_Wo_l[(size_t)D_ * D_];

// ---------------------------------------------------------------------------
// sm_80-level PTX helpers (NO tcgen05 — build target is plain sm_103)
// ---------------------------------------------------------------------------
__device__ __forceinline__ uint32_t smem_u32(const void* p) {
    uint32_t a;
    asm("{ .reg .u64 t; cvta.to.shared.u64 t, %1; cvt.u32.u64 %0, t; }"
        : "=r"(a) : "l"(p));
    return a;
}
__device__ __forceinline__ void ldm4(uint32_t addr, uint32_t* r) {
    asm volatile("ldmatrix.sync.aligned.m8n8.x4.shared.b16 {%0,%1,%2,%3}, [%4];"
                 : "=r"(r[0]), "=r"(r[1]), "=r"(r[2]), "=r"(r[3]) : "r"(addr));
}
__device__ __forceinline__ void mma_bf16(float* c, const uint32_t* a,
                                         const uint32_t* b) {
    asm volatile("mma.sync.aligned.m16n8k16.row.col.f32.bf16.bf16.f32 "
                 "{%0,%1,%2,%3}, {%4,%5,%6,%7}, {%8,%9}, {%0,%1,%2,%3};"
                 : "+f"(c[0]), "+f"(c[1]), "+f"(c[2]), "+f"(c[3])
                 : "r"(a[0]), "r"(a[1]), "r"(a[2]), "r"(a[3]),
                   "r"(b[0]), "r"(b[1]));
}
#define CP_ASYNC16(dst, src) \
    asm volatile("cp.async.ca.shared.global [%0], [%1], 16;" \
                 :: "r"(dst), "l"(src))
#define CP_COMMIT() asm volatile("cp.async.commit_group;" ::: "memory")
#define CP_WAIT0()  asm volatile("cp.async.wait_group 0;" ::: "memory")
#define CP_WAIT1()  asm volatile("cp.async.wait_group 1;" ::: "memory")

__device__ __forceinline__ void bsplit(float v, unsigned short& h,
                                       unsigned short& l) {
    __nv_bfloat16 hb = __float2bfloat16(v);
    float r = v - __bfloat162float(hb);
    __nv_bfloat16 lb = __float2bfloat16(r);
    h = __bfloat16_as_ushort(hb);
    l = __bfloat16_as_ushort(lb);
}

// ---------------------------------------------------------------------------
// Batched weight preconvert (ONE launch): W[K][N] -> Wt[N][K] bf16 hi/lo
// ---------------------------------------------------------------------------
__global__ void wconv_all(
    const float* __restrict__ Wf, const float* __restrict__ Wq,
    const float* __restrict__ Wk, const float* __restrict__ Wv,
    const float* __restrict__ Wo,
    unsigned short* __restrict__ Wfh, unsigned short* __restrict__ Wfl,
    unsigned short* __restrict__ Wqh, unsigned short* __restrict__ Wql,
    unsigned short* __restrict__ Wkh, unsigned short* __restrict__ Wkl,
    unsigned short* __restrict__ Wvh, unsigned short* __restrict__ Wvl,
    unsigned short* __restrict__ Woh, unsigned short* __restrict__ Wol)
{
    const float* W; unsigned short *Th, *Tl; int K;
    switch (blockIdx.z) {
        case 0:  W = Wf; Th = Wfh; Tl = Wfl; K = 1024; break;
        case 1:  W = Wq; Th = Wqh; Tl = Wql; K = 512;  break;
        case 2:  W = Wk; Th = Wkh; Tl = Wkl; K = 512;  break;
        case 3:  W = Wv; Th = Wvh; Tl = Wvl; K = 512;  break;
        default: W = Wo; Th = Woh; Tl = Wol; K = 512;  break;
    }
    int k0 = blockIdx.y * 32, n0 = blockIdx.x * 32;
    if (k0 >= K) return;
    __shared__ float t[32][33];
    int tx = threadIdx.x, ty = threadIdx.y;
    t[ty][tx] = W[(size_t)(k0 + ty) * D_ + n0 + tx];
    __syncthreads();
    float v = t[tx][ty];                 // W[k0+tx][n0+ty]
    unsigned short h, l;
    bsplit(v, h, l);
    size_t o = (size_t)(n0 + ty) * K + k0 + tx;
    Th[o] = h;
    Tl[o] = l;
}

// ---------------------------------------------------------------------------
// 3xBF16 tensor-core GEMM: C[M,N] = A[M,K] @ W[K,N] + bias
// CTA 128x128, K-chunk 32, 8 warps (2x4) of 64x32, 2-stage cp.async pipeline.
// smem rows padded to 40 bf16 (80 B) -> conflict-free ldmatrix.
// ASRC 0: A fp32 (two sources, K-split), inline bsplit + STS.
// ASRC 1: A pre-split bf16 hi/lo [M][K] via cp.async (no convert).
// MODE 0: C fp32 row-major.  MODE 1: head-split scatter to [B,H,S,HD].
// MODE 2: bf16 hi/lo row-major only (for fused activations).
// ---------------------------------------------------------------------------
#define GSTAGE   40960
#define GOFF_AH  0
#define GOFF_AL  10240
#define GOFF_BH  20480
#define GOFF_BL  30720
#define GM_SMEM  (2 * GSTAGE)

__device__ __forceinline__ void gemm_ldA(const float* A0, const float* A1,
                                         int sA0, int sA1, int Ksplit,
                                         int bm, int k0, int tid, float4* av)
{
#pragma unroll
    for (int i = 0; i < 4; i++) {
        int fid = tid + i * 256;
        int m = fid >> 3, kq = fid & 7;
        int kg = k0 + kq * 4;
        const float* src = (kg < Ksplit)
            ? A0 + (size_t)(bm + m) * sA0 + kg
            : A1 + (size_t)(bm + m) * sA1 + (kg - Ksplit);
        av[i] = *(const float4*)src;
    }
}
__device__ __forceinline__ void gemm_stA(unsigned char* stage, int tid,
                                         const float4* av)
{
#pragma unroll
    for (int i = 0; i < 4; i++) {
        int fid = tid + i * 256;
        int m = fid >> 3, kq = fid & 7;
        ushort4 h, l;
        bsplit(av[i].x, h.x, l.x);
        bsplit(av[i].y, h.y, l.y);
        bsplit(av[i].z, h.z, l.z);
        bsplit(av[i].w, h.w, l.w);
        *(ushort4*)(stage + GOFF_AH + m * 80 + kq * 8) = h;
        *(ushort4*)(stage + GOFF_AL + m * 80 + kq * 8) = l;
    }
}
// cp.async a 128x32 pre-split bf16 tile (hi+lo) into stage at offH/offL
__device__ __forceinline__ void gemm_cpPre(uint32_t stage_u32,
                                           uint32_t offH, uint32_t offL,
                                           const unsigned short* Th,
                                           const unsigned short* Tl,
                                           int row0, int K, int k0, int tid)
{
#pragma unroll
    for (int i = 0; i < 2; i++) {
        int fid = tid + i * 256;
        int r = fid >> 2, c16 = fid & 3;
        size_t gs = (size_t)(row0 + r) * K + k0 + c16 * 8;
        CP_ASYNC16(stage_u32 + offH + r * 80 + c16 * 16, (const char*)(Th + gs));
        CP_ASYNC16(stage_u32 + offL + r * 80 + c16 * 16, (const char*)(Tl + gs));
    }
}

template <int MODE, int ASRC>
__global__ __launch_bounds__(256) void mm_mma(
    const float* __restrict__ A0, const float* __restrict__ A1,
    int sA0, int sA1, int Ksplit,
    const unsigned short* __restrict__ Ah, const unsigned short* __restrict__ Al,
    const unsigned short* __restrict__ Bh, const unsigned short* __restrict__ Bl,
    const float* __restrict__ bias, float* __restrict__ C,
    unsigned short* __restrict__ Ch, unsigned short* __restrict__ Cl,
    int N, int K)
{
    extern __shared__ __align__(16) unsigned char smem[];
    const uint32_t sb = smem_u32(smem);
    const int tid = threadIdx.x, lane = tid & 31, wid = tid >> 5;
    const int wy = wid >> 2, wx = wid & 3;
    const int bn = blockIdx.x * 128, bm = blockIdx.y * 128;
    const int NC = K / 32;

    float acc[4][4][4];
#pragma unroll
    for (int i = 0; i < 4; i++)
#pragma unroll
        for (int j = 0; j < 4; j++)
#pragma unroll
            for (int q = 0; q < 4; q++) acc[i][j][q] = 0.f;

    const uint32_t arow = (wy * 64 + (lane & 15)) * 80 + (lane >> 4) * 16;
    const uint32_t brow = (wx * 32 + (lane & 15)) * 80 + (lane >> 4) * 16;

    float4 av[4];
    if (ASRC == 0) {
        gemm_ldA(A0, A1, sA0, sA1, Ksplit, bm, 0, tid, av);
        gemm_cpPre(sb, GOFF_BH, GOFF_BL, Bh, Bl, bn, K, 0, tid);
        CP_COMMIT();
        gemm_stA(smem, tid, av);
    } else {
        gemm_cpPre(sb, GOFF_AH, GOFF_AL, Ah, Al, bm, K, 0, tid);
        gemm_cpPre(sb, GOFF_BH, GOFF_BL, Bh, Bl, bn, K, 0, tid);
        CP_COMMIT();
    }

    for (int c = 0; c < NC; c++) {
        const int st = c & 1;
        const bool more = (c + 1 < NC);
        if (more) {
            uint32_t s1 = sb + ((c + 1) & 1) * GSTAGE;
            if (ASRC == 0) {
                gemm_ldA(A0, A1, sA0, sA1, Ksplit, bm, (c + 1) * 32, tid, av);
            } else {
                gemm_cpPre(s1, GOFF_AH, GOFF_AL, Ah, Al, bm, K, (c + 1) * 32, tid);
            }
            gemm_cpPre(s1, GOFF_BH, GOFF_BL, Bh, Bl, bn, K, (c + 1) * 32, tid);
            CP_COMMIT();
        }
        if (more) { CP_WAIT1(); } else { CP_WAIT0(); }
        __syncthreads();

        const uint32_t s0 = sb + st * GSTAGE;
#pragma unroll
        for (int ks = 0; ks < 2; ks++) {
            uint32_t ah[4][4], al[4][4];
#pragma unroll
            for (int mt = 0; mt < 4; mt++) {
                ldm4(s0 + GOFF_AH + arow + mt * 1280 + ks * 32, ah[mt]);
                ldm4(s0 + GOFF_AL + arow + mt * 1280 + ks * 32, al[mt]);
            }
#pragma unroll
            for (int nb = 0; nb < 2; nb++) {
                uint32_t bh4[4], bl4[4];
                ldm4(s0 + GOFF_BH + brow + nb * 1280 + ks * 32, bh4);
                ldm4(s0 + GOFF_BL + brow + nb * 1280 + ks * 32, bl4);
                uint32_t th0[2] = {bh4[0], bh4[2]}, th1[2] = {bh4[1], bh4[3]};
                uint32_t tl0[2] = {bl4[0], bl4[2]}, tl1[2] = {bl4[1], bl4[3]};
#pragma unroll
                for (int mt = 0; mt < 4; mt++) {
                    mma_bf16(acc[mt][2 * nb],     ah[mt], th0);
                    mma_bf16(acc[mt][2 * nb + 1], ah[mt], th1);
                    mma_bf16(acc[mt][2 * nb],     ah[mt], tl0);
                    mma_bf16(acc[mt][2 * nb + 1], ah[mt], tl1);
                    mma_bf16(acc[mt][2 * nb],     al[mt], th0);
                    mma_bf16(acc[mt][2 * nb + 1], al[mt], th1);
                }
            }
        }
        if (ASRC == 0 && more) gemm_stA(smem + ((c + 1) & 1) * GSTAGE, tid, av);
        __syncthreads();
    }

    // epilogue
#pragma unroll
    for (int mt = 0; mt < 4; mt++) {
#pragma unroll
        for (int nt = 0; nt < 4; nt++) {
            int r0 = bm + wy * 64 + mt * 16 + (lane >> 2);
            int col = bn + wx * 32 + nt * 8 + 2 * (lane & 3);
            float b0 = bias[col], b1 = bias[col + 1];
            float2 v0 = make_float2(acc[mt][nt][0] + b0, acc[mt][nt][1] + b1);
            float2 v1 = make_float2(acc[mt][nt][2] + b0, acc[mt][nt][3] + b1);
            if (MODE == 0) {
                *(float2*)(C + (size_t)r0 * N + col) = v0;
                *(float2*)(C + (size_t)(r0 + 8) * N + col) = v1;
            } else if (MODE == 1) {
                int hh = col >> 6, dd = col & (HD_ - 1);
                int bb0 = r0 >> 11, ss0 = r0 & (S_ - 1);
                *(float2*)(C + (((size_t)bb0 * H_ + hh) * S_ + ss0) * HD_ + dd) = v0;
                int r1 = r0 + 8;
                int bb1 = r1 >> 11, ss1 = r1 & (S_ - 1);
                *(float2*)(C + (((size_t)bb1 * H_ + hh) * S_ + ss1) * HD_ + dd) = v1;
            } else {
                unsigned short hx, lx, hy, ly;
                bsplit(v0.x, hx, lx); bsplit(v0.y, hy, ly);
                *(ushort2*)(Ch + (size_t)r0 * N + col) = make_ushort2(hx, hy);
                *(ushort2*)(Cl + (size_t)r0 * N + col) = make_ushort2(lx, ly);
                bsplit(v1.x, hx, lx); bsplit(v1.y, hy, ly);
                *(ushort2*)(Ch + (size_t)(r0 + 8) * N + col) = make_ushort2(hx, hy);
                *(ushort2*)(Cl + (size_t)(r0 + 8) * N + col) = make_ushort2(lx, ly);
            }
        }
    }
}

// ---------------------------------------------------------------------------
// Tensor-core flash attention with masked softmax + L1 renorm.
// CTA: 128 q-rows x one (b,h); 8 warps x 16 rows; 64-key blocks.
// Pipelined: M double-buffered (cp.async, 2 stages), K/V prefetched into
// registers one block ahead (LDG latency hidden behind mma+softmax).
// ---------------------------------------------------------------------------
#define OQH 0
#define OQL 18432
#define OKH 36864
#define OKL 46080
#define OVH 55296
#define OVL 64512
#define OMS 73728
#define MSTG 34816
#define ATTN_SMEM (73728 + 2 * 34816)   // 143360

__device__ __forceinline__ void attn_ldkv(const float* Kp, const float* Vp,
                                          int kk0, int tid,
                                          float4* kr, float4* vr)
{
#pragma unroll
    for (int i = 0; i < 4; i++) {
        int fid = tid + i * 256;
        int row = fid >> 4, c4 = (fid & 15) * 4;
        kr[i] = *(const float4*)(Kp + (size_t)(kk0 + row) * HD_ + c4);
        vr[i] = *(const float4*)(Vp + (size_t)(kk0 + row) * HD_ + c4);
    }
}
__device__ __forceinline__ void attn_stkv(unsigned char* smem, int tid,
                                          const float4* kr, const float4* vr)
{
#pragma unroll
    for (int i = 0; i < 4; i++) {
        int fid = tid + i * 256;
        int row = fid >> 4, c4 = (fid & 15) * 4;
        ushort4 kh, kl;
        bsplit(kr[i].x, kh.x, kl.x); bsplit(kr[i].y, kh.y, kl.y);
        bsplit(kr[i].z, kh.z, kl.z); bsplit(kr[i].w, kh.w, kl.w);
        *(ushort4*)(smem + OKH + row * 144 + c4 * 2) = kh;
        *(ushort4*)(smem + OKL + row * 144 + c4 * 2) = kl;
        unsigned short vh, vl;
        bsplit(vr[i].x, vh, vl);
        *(unsigned short*)(smem + OVH + (c4 + 0) * 144 + row * 2) = vh;
        *(unsigned short*)(smem + OVL + (c4 + 0) * 144 + row * 2) = vl;
        bsplit(vr[i].y, vh, vl);
        *(unsigned short*)(smem + OVH + (c4 + 1) * 144 + row * 2) = vh;
        *(unsigned short*)(smem + OVL + (c4 + 1) * 144 + row * 2) = vl;
        bsplit(vr[i].z, vh, vl);
        *(unsigned short*)(smem + OVH + (c4 + 2) * 144 + row * 2) = vh;
        *(unsigned short*)(smem + OVL + (c4 + 2) * 144 + row * 2) = vl;
        bsplit(vr[i].w, vh, vl);
        *(unsigned short*)(smem + OVH + (c4 + 3) * 144 + row * 2) = vh;
        *(unsigned short*)(smem + OVL + (c4 + 3) * 144 + row * 2) = vl;
    }
}
__device__ __forceinline__ void attn_cpM(uint32_t sb, int stage,
                                         const float* Mp, int q0, int kk0,
                                         int tid)
{
#pragma unroll
    for (int i = 0; i < 8; i++) {
        int fid = tid + i * 256;
        int row = fid >> 4, c16 = fid & 15;
        CP_ASYNC16(sb + OMS + stage * MSTG + row * 272 + c16 * 16,
                   (const char*)(Mp + (size_t)(q0 + row) * S_ + kk0 + c16 * 4));
    }
}

__global__ __launch_bounds__(256) void attn_mma(
    const float* __restrict__ Q, const float* __restrict__ K,
    const float* __restrict__ V, const float* __restrict__ Mm,
    float* __restrict__ Out)
{
    extern __shared__ __align__(16) unsigned char smem[];
    const uint32_t sb = smem_u32(smem);

    const int q0 = blockIdx.x * 128;
    const int h  = blockIdx.y;
    const int b  = blockIdx.z;
    const int tid = threadIdx.x, lane = tid & 31, w = tid >> 5;
    const int qr = lane >> 2, qc = lane & 3;

    const size_t bh = (size_t)b * H_ + h;
    const float* Qp = Q + bh * S_ * HD_;
    const float* Kp = K + bh * S_ * HD_;
    const float* Vp = V + bh * S_ * HD_;
    const float* Mp = Mm + (size_t)b * S_ * S_;

    // prologue: M(0) in flight, K/V(0) in registers
    attn_cpM(sb, 0, Mp, q0, 0, tid);
    CP_COMMIT();
    float4 kr[4], vr[4];
    attn_ldkv(Kp, Vp, 0, tid, kr, vr);

    // load Q tile (128x64), split to bf16 hi/lo
#pragma unroll
    for (int i = 0; i < 8; i++) {
        int fid = tid + i * 256;
        int row = fid >> 4, c4 = (fid & 15) * 4;
        float4 v = *(const float4*)(Qp + (size_t)(q0 + row) * HD_ + c4);
        ushort4 hh, ll;
        bsplit(v.x, hh.x, ll.x); bsplit(v.y, hh.y, ll.y);
        bsplit(v.z, hh.z, ll.z); bsplit(v.w, hh.w, ll.w);
        *(ushort4*)(smem + OQH + row * 144 + c4 * 2) = hh;
        *(ushort4*)(smem + OQL + row * 144 + c4 * 2) = ll;
    }

    float O[8][4];
#pragma unroll
    for (int t = 0; t < 8; t++)
#pragma unroll
        for (int j = 0; j < 4; j++) O[t][j] = 0.f;
    float m0 = -1e30f, m1 = -1e30f, Z0 = 0.f, Z1 = 0.f, T0 = 0.f, T1 = 0.f;

    const uint32_t qrow = (w * 16 + (lane & 15)) * 144 + (lane >> 4) * 16;
    const uint32_t klrow = ((lane & 15)) * 144 + (lane >> 4) * 16;

    const int NB = S_ / 64;
    for (int kb = 0; kb < NB; kb++) {
        const int st = kb & 1;
        const bool more = (kb + 1 < NB);

        // stage K/V(kb) from registers into smem
        attn_stkv(smem, tid, kr, vr);
        // issue M(kb+1) into the other stage
        if (more) {
            attn_cpM(sb, st ^ 1, Mp, q0, (kb + 1) * 64, tid);
            CP_COMMIT();
        }
        // ensure M(kb) landed (issued last iteration / prologue)
        if (more) { CP_WAIT1(); } else { CP_WAIT0(); }
        __syncthreads();
        // prefetch K/V(kb+1) into registers — hidden behind the mma below
        if (more) attn_ldkv(Kp, Vp, (kb + 1) * 64, tid, kr, vr);

        // ---- S = Q K^T (3xBF16) ----
        float S[8][4];
#pragma unroll
        for (int t = 0; t < 8; t++)
#pragma unroll
            for (int j = 0; j < 4; j++) S[t][j] = 0.f;
#pragma unroll
        for (int ks = 0; ks < 4; ks++) {
            uint32_t ah[4], al[4];
            ldm4(sb + OQH + qrow + ks * 32, ah);
            ldm4(sb + OQL + qrow + ks * 32, al);
#pragma unroll
            for (int nb = 0; nb < 4; nb++) {
                uint32_t bh4[4], bl4[4];
                ldm4(sb + OKH + klrow + nb * 2304 + ks * 32, bh4);
                ldm4(sb + OKL + klrow + nb * 2304 + ks * 32, bl4);
                uint32_t th0[2] = {bh4[0], bh4[2]}, th1[2] = {bh4[1], bh4[3]};
                uint32_t tl0[2] = {bl4[0], bl4[2]}, tl1[2] = {bl4[1], bl4[3]};
                mma_bf16(S[2 * nb],     ah, th0);
                mma_bf16(S[2 * nb + 1], ah, th1);
                mma_bf16(S[2 * nb],     ah, tl0);
                mma_bf16(S[2 * nb + 1], ah, tl1);
                mma_bf16(S[2 * nb],     al, th0);
                mma_bf16(S[2 * nb + 1], al, th1);
            }
        }

        // ---- masked scale + online softmax (M from stage st) ----
        const unsigned char* msp = smem + OMS + st * MSTG;
        const int mr0 = (w * 16 + qr) * 272 + qc * 8;
        float bm0 = -1e30f, bm1 = -1e30f;
        float mva[8], mvb[8], mvc[8], mvd[8];
#pragma unroll
        for (int t = 0; t < 8; t++) {
            float2 ma = *(const float2*)(msp + mr0 + t * 32);
            float2 mb = *(const float2*)(msp + mr0 + 8 * 272 + t * 32);
            mva[t] = ma.x; mvb[t] = ma.y; mvc[t] = mb.x; mvd[t] = mb.y;
            S[t][0] *= 0.125f * ma.x;
            S[t][1] *= 0.125f * ma.y;
            S[t][2] *= 0.125f * mb.x;
            S[t][3] *= 0.125f * mb.y;
            bm0 = fmaxf(bm0, fmaxf(S[t][0], S[t][1]));
            bm1 = fmaxf(bm1, fmaxf(S[t][2], S[t][3]));
        }
        bm0 = fmaxf(bm0, __shfl_xor_sync(0xffffffffu, bm0, 1));
        bm0 = fmaxf(bm0, __shfl_xor_sync(0xffffffffu, bm0, 2));
        bm1 = fmaxf(bm1, __shfl_xor_sync(0xffffffffu, bm1, 1));
        bm1 = fmaxf(bm1, __shfl_xor_sync(0xffffffffu, bm1, 2));
        float nm0 = fmaxf(m0, bm0), nm1 = fmaxf(m1, bm1);
        float f0 = __expf(m0 - nm0), f1 = __expf(m1 - nm1);
        m0 = nm0; m1 = nm1;
        Z0 *= f0; Z1 *= f1; T0 *= f0; T1 *= f1;
#pragma unroll
        for (int t = 0; t < 8; t++) {
            O[t][0] *= f0; O[t][1] *= f0; O[t][2] *= f1; O[t][3] *= f1;
            float e0 = __expf(S[t][0] - nm0);
            float e1 = __expf(S[t][1] - nm0);
            float e2 = __expf(S[t][2] - nm1);
            float e3 = __expf(S[t][3] - nm1);
            Z0 += e0 + e1; Z1 += e2 + e3;
            float p0 = e0 * mva[t], p1 = e1 * mvb[t];
            float p2 = e2 * mvc[t], p3 = e3 * mvd[t];
            T0 += p0 + p1; T1 += p2 + p3;
            S[t][0] = p0; S[t][1] = p1; S[t][2] = p2; S[t][3] = p3;
        }

        // ---- pack P to bf16 hi/lo A-fragments ----
        uint32_t phi[4][4], plo[4][4];
#pragma unroll
        for (int kt = 0; kt < 4; kt++) {
            unsigned short h0, l0, h1, l1;
            bsplit(S[2 * kt][0], h0, l0); bsplit(S[2 * kt][1], h1, l1);
            phi[kt][0] = (uint32_t)h0 | ((uint32_t)h1 << 16);
            plo[kt][0] = (uint32_t)l0 | ((uint32_t)l1 << 16);
            bsplit(S[2 * kt][2], h0, l0); bsplit(S[2 * kt][3], h1, l1);
            phi[kt][1] = (uint32_t)h0 | ((uint32_t)h1 << 16);
            plo[kt][1] = (uint32_t)l0 | ((uint32_t)l1 << 16);
            bsplit(S[2 * kt + 1][0], h0, l0); bsplit(S[2 * kt + 1][1], h1, l1);
            phi[kt][2] = (uint32_t)h0 | ((uint32_t)h1 << 16);
            plo[kt][2] = (uint32_t)l0 | ((uint32_t)l1 << 16);
            bsplit(S[2 * kt + 1][2], h0, l0); bsplit(S[2 * kt + 1][3], h1, l1);
            phi[kt][3] = (uint32_t)h0 | ((uint32_t)h1 << 16);
            plo[kt][3] = (uint32_t)l0 | ((uint32_t)l1 << 16);
        }

        // ---- O += P @ V ----
#pragma unroll
        for (int kt = 0; kt < 4; kt++) {
#pragma unroll
            for (int nb = 0; nb < 4; nb++) {
                uint32_t vh4[4], vl4[4];
                ldm4(sb + OVH + klrow + nb * 2304 + kt * 32, vh4);
                ldm4(sb + OVL + klrow + nb * 2304 + kt * 32, vl4);
                uint32_t th0[2] = {vh4[0], vh4[2]}, th1[2] = {vh4[1], vh4[3]};
                uint32_t tl0[2] = {vl4[0], vl4[2]}, tl1[2] = {vl4[1], vl4[3]};
                mma_bf16(O[2 * nb],     phi[kt], th0);
                mma_bf16(O[2 * nb + 1], phi[kt], th1);
                mma_bf16(O[2 * nb],     phi[kt], tl0);
                mma_bf16(O[2 * nb + 1], phi[kt], tl1);
                mma_bf16(O[2 * nb],     plo[kt], th0);
                mma_bf16(O[2 * nb + 1], plo[kt], th1);
            }
        }
        __syncthreads();
    }

    // ---- finalize ----
    T0 += __shfl_xor_sync(0xffffffffu, T0, 1);
    T0 += __shfl_xor_sync(0xffffffffu, T0, 2);
    T1 += __shfl_xor_sync(0xffffffffu, T1, 1);
    T1 += __shfl_xor_sync(0xffffffffu, T1, 2);
    Z0 += __shfl_xor_sync(0xffffffffu, Z0, 1);
    Z0 += __shfl_xor_sync(0xffffffffu, Z0, 2);
    Z1 += __shfl_xor_sync(0xffffffffu, Z1, 1);
    Z1 += __shfl_xor_sync(0xffffffffu, Z1, 2);
    float inv0 = 1.0f / (T0 + EPS_ * Z0);
    float inv1 = 1.0f / (T1 + EPS_ * Z1);

    int gr0 = q0 + w * 16 + qr;
#pragma unroll
    for (int t = 0; t < 8; t++) {
        int d = t * 8 + 2 * qc;
        float2 v0 = make_float2(O[t][0] * inv0, O[t][1] * inv0);
        float2 v1 = make_float2(O[t][2] * inv1, O[t][3] * inv1);
        *(float2*)(Out + ((size_t)b * S_ + gr0) * D_ + h * HD_ + d) = v0;
        *(float2*)(Out + ((size_t)b * S_ + gr0 + 8) * D_ + h * HD_ + d) = v1;
    }
}

// ---------------------------------------------------------------------------
// Host
// ---------------------------------------------------------------------------
extern "C" void kernel_launch(void* const* d_in, const int* in_sizes, int n_in,
                              void* d_out, int out_size)
{
    const float* gene = (const float*)d_in[0];
    const float* expr = (const float*)d_in[1];
    const float* Mm   = (const float*)d_in[2];
    const float* Wf   = (const float*)d_in[3];
    const float* bf   = (const float*)d_in[4];
    const float* Wq   = (const float*)d_in[5];
    const float* bq   = (const float*)d_in[6];
    const float* Wk   = (const float*)d_in[7];
    const float* bk   = (const float*)d_in[8];
    const float* Wv   = (const float*)d_in[9];
    const float* bv   = (const float*)d_in[10];
    const float* Wo   = (const float*)d_in[11];
    const float* bo   = (const float*)d_in[12];
    float* out = (float*)d_out;

    float *Qb, *Kb, *Vb, *Ab;
    unsigned short *Fh, *Fl;
    unsigned short *Wfh, *Wfl, *Wqh, *Wql, *Wkh, *Wkl, *Wvh, *Wvl, *Woh, *Wol;
    cudaGetSymbolAddress((void**)&Qb,  g_Q);
    cudaGetSymbolAddress((void**)&Kb,  g_K);
    cudaGetSymbolAddress((void**)&Vb,  g_V);
    cudaGetSymbolAddress((void**)&Ab,  g_attn);
    cudaGetSymbolAddress((void**)&Fh,  g_fus_h);
    cudaGetSymbolAddress((void**)&Fl,  g_fus_l);
    cudaGetSymbolAddress((void**)&Wfh, g_Wf_h);
    cudaGetSymbolAddress((void**)&Wfl, g_Wf_l);
    cudaGetSymbolAddress((void**)&Wqh, g_Wq_h);
    cudaGetSymbolAddress((void**)&Wql, g_Wq_l);
    cudaGetSymbolAddress((void**)&Wkh, g_Wk_h);
    cudaGetSymbolAddress((void**)&Wkl, g_Wk_l);
    cudaGetSymbolAddress((void**)&Wvh, g_Wv_h);
    cudaGetSymbolAddress((void**)&Wvl, g_Wv_l);
    cudaGetSymbolAddress((void**)&Woh, g_Wo_h);
    cudaGetSymbolAddress((void**)&Wol, g_Wo_l);

    cudaFuncSetAttribute(mm_mma<2, 0>, cudaFuncAttributeMaxDynamicSharedMemorySize, GM_SMEM);
    cudaFuncSetAttribute(mm_mma<1, 1>, cudaFuncAttributeMaxDynamicSharedMemorySize, GM_SMEM);
    cudaFuncSetAttribute(mm_mma<1, 0>, cudaFuncAttributeMaxDynamicSharedMemorySize, GM_SMEM);
    cudaFuncSetAttribute(mm_mma<0, 0>, cudaFuncAttributeMaxDynamicSharedMemorySize, GM_SMEM);
    cudaFuncSetAttribute(attn_mma, cudaFuncAttributeMaxDynamicSharedMemorySize, ATTN_SMEM);

    // 1) all weight conversions in ONE launch
    wconv_all<<<dim3(16, 32, 5), dim3(32, 32)>>>(
        Wf, Wq, Wk, Wv, Wo,
        Wfh, Wfl, Wqh, Wql, Wkh, Wkl, Wvh, Wvl, Woh, Wol);

    dim3 gg(D_ / 128, ROWS_ / 128);   // (4, 64)

    // 2) fused = concat(gene, expr) @ Wf + bf  -> bf16 hi/lo only
    mm_mma<2, 0><<<gg, 256, GM_SMEM>>>(gene, expr, D_, D_, D_,
                                       nullptr, nullptr, Wfh, Wfl, bf,
                                       nullptr, Fh, Fl, D_, 2 * D_);
    // 3,4) Q, K from pre-split fused (cp.async A path), head-split epilogue
    mm_mma<1, 1><<<gg, 256, GM_SMEM>>>(nullptr, nullptr, 0, 0, 0,
                                       Fh, Fl, Wqh, Wql, bq,
                                       Qb, nullptr, nullptr, D_, D_);
    mm_mma<1, 1><<<gg, 256, GM_SMEM>>>(nullptr, nullptr, 0, 0, 0,
                                       Fh, Fl, Wkh, Wkl, bk,
                                       Kb, nullptr, nullptr, D_, D_);
    // 5) V from expr (fp32 A path)
    mm_mma<1, 0><<<gg, 256, GM_SMEM>>>(expr, expr, D_, D_, D_,
                                       nullptr, nullptr, Wvh, Wvl, bv,
                                       Vb, nullptr, nullptr, D_, D_);

    // 6) flash attention
    attn_mma<<<dim3(S_ / 128, H_, B_), 256, ATTN_SMEM>>>(Qb, Kb, Vb, Mm, Ab);

    // 7) out = attn @ Wo + bo
    mm_mma<0, 0><<<gg, 256, GM_SMEM>>>(Ab, Ab, D_, D_, D_,
                                       nullptr, nullptr, Woh, Wol, bo,
                                       out, nullptr, nullptr, D_, D_);
}